// round 1
// baseline (speedup 1.0000x reference)
#include <cuda_runtime.h>
#include <cstdint>

#define TILE    128
#define THREADS 256

// ---------------- device scratch (no allocs allowed) ----------------
#define N_MAX 50048
__device__ float g_send_agg[N_MAX * 32];
__device__ float g_recv_agg[N_MAX * 32];
__device__ float g_e2g[64 * 32];
__device__ float g_n2g[64 * 32];

// ---------------- shared memory layout (float offsets) ----------------
#define XS_OFF    0
#define XS_STRIDE 129          // 128 rows (k) x 128 cols (tile), padded
#define W1_OFF    16512        // 128*128
#define W2_OFF    32896        // 128*32
#define YS_OFF    36992        // 128*33
#define YS_STRIDE 33
#define B1_OFF    41216        // 128
#define B2_OFF    41344        // 32
#define GAM_OFF   41376        // 32
#define BET_OFF   41408        // 32
#define AGG_OFF   41440        // 64*32 per-graph staging
#define IDX0_OFF  43488        // rows / batch (int)
#define IDX1_OFF  43616        // cols (int)
#define IDX2_OFF  43744        // graph id (int)
#define MU_OFF    43872        // 128
#define RS_OFF    44000        // 128
#define SMEM_FLOATS 44128
#define SMEM_BYTES  (SMEM_FLOATS * 4)

// ======================================================================
// Shared MLP core: X (SMEM, [k][i] layout) @ W1 -> relu -> @ W2 -> relu
// 256 threads, thread (ty,tx) owns 8 rows x 8 cols of H, 8 rows x 2 cols of Y
// ======================================================================
__device__ __forceinline__ void mlp_core(float* __restrict__ sm, int tid)
{
    float* Xs  = sm + XS_OFF;
    float* W1s = sm + W1_OFF;
    float* W2s = sm + W2_OFF;
    float* Ys  = sm + YS_OFF;
    float* b1s = sm + B1_OFF;
    float* b2s = sm + B2_OFF;

    const int ty = tid >> 4;   // 0..15 -> row block
    const int tx = tid & 15;   // 0..15 -> col block

    // ---- GEMM1: H[128x128] = relu(X @ W1 + b1) ----
    float acc[8][8];
#pragma unroll
    for (int i = 0; i < 8; i++)
#pragma unroll
        for (int j = 0; j < 8; j++) acc[i][j] = 0.f;

#pragma unroll 4
    for (int k = 0; k < 128; k++) {
        float a[8], b[8];
#pragma unroll
        for (int i = 0; i < 8; i++) a[i] = Xs[k * XS_STRIDE + ty * 8 + i];
        float4 b0 = *(const float4*)&W1s[k * 128 + tx * 8];
        float4 b1v = *(const float4*)&W1s[k * 128 + tx * 8 + 4];
        b[0] = b0.x; b[1] = b0.y; b[2] = b0.z; b[3] = b0.w;
        b[4] = b1v.x; b[5] = b1v.y; b[6] = b1v.z; b[7] = b1v.w;
#pragma unroll
        for (int i = 0; i < 8; i++)
#pragma unroll
            for (int j = 0; j < 8; j++)
                acc[i][j] = fmaf(a[i], b[j], acc[i][j]);
    }
    __syncthreads();   // all X reads done before overwrite

    // write relu(H + b1) transposed into Xs buffer as Hs[k=l][i]
#pragma unroll
    for (int j = 0; j < 8; j++) {
        float bj = b1s[tx * 8 + j];
#pragma unroll
        for (int i = 0; i < 8; i++)
            Xs[(tx * 8 + j) * XS_STRIDE + ty * 8 + i] = fmaxf(acc[i][j] + bj, 0.f);
    }
    __syncthreads();

    // ---- GEMM2: Y[128x32] = relu(H @ W2 + b2) ----
    float acc2[8][2];
#pragma unroll
    for (int i = 0; i < 8; i++) { acc2[i][0] = 0.f; acc2[i][1] = 0.f; }

#pragma unroll 4
    for (int k = 0; k < 128; k++) {
        float a[8];
#pragma unroll
        for (int i = 0; i < 8; i++) a[i] = Xs[k * XS_STRIDE + ty * 8 + i];
        float c0 = W2s[k * 32 + tx * 2];
        float c1 = W2s[k * 32 + tx * 2 + 1];
#pragma unroll
        for (int i = 0; i < 8; i++) {
            acc2[i][0] = fmaf(a[i], c0, acc2[i][0]);
            acc2[i][1] = fmaf(a[i], c1, acc2[i][1]);
        }
    }
#pragma unroll
    for (int jc = 0; jc < 2; jc++) {
        float bj = b2s[tx * 2 + jc];
#pragma unroll
        for (int i = 0; i < 8; i++)
            Ys[(ty * 8 + i) * YS_STRIDE + tx * 2 + jc] = fmaxf(acc2[i][jc] + bj, 0.f);
    }
    __syncthreads();
}

__device__ __forceinline__ void ln_stats(float* __restrict__ sm, int tid)
{
    float* Ys  = sm + YS_OFF;
    float* mus = sm + MU_OFF;
    float* rss = sm + RS_OFF;
    if (tid < TILE) {
        float s = 0.f, s2 = 0.f;
#pragma unroll
        for (int f = 0; f < 32; f++) {
            float v = Ys[tid * YS_STRIDE + f];
            s += v;
            s2 = fmaf(v, v, s2);
        }
        float mu  = s * (1.f / 32.f);
        float var = s2 * (1.f / 32.f) - mu * mu;
        mus[tid] = mu;
        rss[tid] = rsqrtf(var + 1e-5f);
    }
    __syncthreads();
}

// ======================================================================
// Edge kernel: gather -> MLP -> ReLU -> LN -> write + scatter atomics
// ======================================================================
__global__ __launch_bounds__(THREADS)
void edge_kernel(const float* __restrict__ edge_attr,
                 const float* __restrict__ node_attr,
                 const float* __restrict__ global_attr,
                 const int*   __restrict__ edge_index,
                 const int*   __restrict__ batch,
                 const float* __restrict__ W1, const float* __restrict__ b1,
                 const float* __restrict__ W2, const float* __restrict__ b2,
                 const float* __restrict__ gam, const float* __restrict__ bet,
                 float* __restrict__ out_edge, int E)
{
    extern __shared__ float sm[];
    float* Xs   = sm + XS_OFF;
    float* W1s  = sm + W1_OFF;
    float* W2s  = sm + W2_OFF;
    float* Ys   = sm + YS_OFF;
    float* aggs = sm + AGG_OFF;
    int*   rows_s = (int*)(sm + IDX0_OFF);
    int*   cols_s = (int*)(sm + IDX1_OFF);
    int*   gb_s   = (int*)(sm + IDX2_OFF);
    float* mus  = sm + MU_OFF;
    float* rss  = sm + RS_OFF;

    const int tid = threadIdx.x;
    const int e0  = blockIdx.x * TILE;

    if (tid < TILE) {
        int ge = e0 + tid;
        int r = 0, c = 0;
        if (ge < E) { r = edge_index[ge]; c = edge_index[E + ge]; }
        rows_s[tid] = r;
        cols_s[tid] = c;
        gb_s[tid]   = batch[r];
    }
    for (int i = tid; i < 128 * 128; i += THREADS) W1s[i] = W1[i];
    for (int i = tid; i < 128 * 32;  i += THREADS) W2s[i] = W2[i];
    for (int i = tid; i < 64 * 32;   i += THREADS) aggs[i] = 0.f;
    if (tid < 128) sm[B1_OFF + tid] = b1[tid];
    if (tid < 32) {
        sm[B2_OFF + tid]  = b2[tid];
        sm[GAM_OFF + tid] = gam[tid];
        sm[BET_OFF + tid] = bet[tid];
    }
    __syncthreads();

    // gather X: [receiver | sender | edge_attr | g2e], stored [k][i]
    for (int idx = tid; idx < TILE * 32; idx += THREADS) {
        int e = idx >> 5, f = idx & 31;
        int ge = e0 + e;
        float rv = 0.f, sv = 0.f, ev = 0.f, gv = 0.f;
        if (ge < E) {
            rv = node_attr[cols_s[e] * 32 + f];          // receiver = node_attr[col]
            sv = node_attr[rows_s[e] * 32 + f];          // sender   = node_attr[row]
            ev = edge_attr[(size_t)ge * 32 + f];
            gv = global_attr[gb_s[e] * 32 + f];
        }
        Xs[f * XS_STRIDE + e]        = rv;
        Xs[(32 + f) * XS_STRIDE + e] = sv;
        Xs[(64 + f) * XS_STRIDE + e] = ev;
        Xs[(96 + f) * XS_STRIDE + e] = gv;
    }
    __syncthreads();

    mlp_core(sm, tid);
    ln_stats(sm, tid);

    for (int idx = tid; idx < TILE * 32; idx += THREADS) {
        int e = idx >> 5, f = idx & 31;
        int ge = e0 + e;
        if (ge < E) {
            float v = (Ys[e * YS_STRIDE + f] - mus[e]) * rss[e] * sm[GAM_OFF + f]
                      + sm[BET_OFF + f];
            out_edge[(size_t)ge * 32 + f] = v;
            atomicAdd(&g_send_agg[rows_s[e] * 32 + f], v);
            atomicAdd(&g_recv_agg[cols_s[e] * 32 + f], v);
            atomicAdd(&aggs[gb_s[e] * 32 + f], v);       // shared staging for e2g
        }
    }
    __syncthreads();
    for (int i = tid; i < 64 * 32; i += THREADS)
        atomicAdd(&g_e2g[i], aggs[i]);
}

// ======================================================================
// Node kernel: gather -> MLP -> ReLU -> LN -> write + n2g staging
// ======================================================================
__global__ __launch_bounds__(THREADS)
void node_kernel(const float* __restrict__ node_attr,
                 const float* __restrict__ global_attr,
                 const int*   __restrict__ batch,
                 const float* __restrict__ W1, const float* __restrict__ b1,
                 const float* __restrict__ W2, const float* __restrict__ b2,
                 const float* __restrict__ gam, const float* __restrict__ bet,
                 float* __restrict__ out_node, int N)
{
    extern __shared__ float sm[];
    float* Xs   = sm + XS_OFF;
    float* W1s  = sm + W1_OFF;
    float* W2s  = sm + W2_OFF;
    float* Ys   = sm + YS_OFF;
    float* aggs = sm + AGG_OFF;
    int*   bat_s = (int*)(sm + IDX0_OFF);
    float* mus  = sm + MU_OFF;
    float* rss  = sm + RS_OFF;

    const int tid = threadIdx.x;
    const int n0  = blockIdx.x * TILE;

    if (tid < TILE) {
        int gn = n0 + tid;
        bat_s[tid] = (gn < N) ? batch[gn] : 0;
    }
    for (int i = tid; i < 128 * 128; i += THREADS) W1s[i] = W1[i];
    for (int i = tid; i < 128 * 32;  i += THREADS) W2s[i] = W2[i];
    for (int i = tid; i < 64 * 32;   i += THREADS) aggs[i] = 0.f;
    if (tid < 128) sm[B1_OFF + tid] = b1[tid];
    if (tid < 32) {
        sm[B2_OFF + tid]  = b2[tid];
        sm[GAM_OFF + tid] = gam[tid];
        sm[BET_OFF + tid] = bet[tid];
    }
    __syncthreads();

    // X: [node_attr | g2n | recv_agg | send_agg]
    for (int idx = tid; idx < TILE * 32; idx += THREADS) {
        int n = idx >> 5, f = idx & 31;
        int gn = n0 + n;
        float nv = 0.f, gv = 0.f, rv = 0.f, sv = 0.f;
        if (gn < N) {
            nv = node_attr[(size_t)gn * 32 + f];
            gv = global_attr[bat_s[n] * 32 + f];
            rv = g_recv_agg[gn * 32 + f];
            sv = g_send_agg[gn * 32 + f];
        }
        Xs[f * XS_STRIDE + n]        = nv;
        Xs[(32 + f) * XS_STRIDE + n] = gv;
        Xs[(64 + f) * XS_STRIDE + n] = rv;
        Xs[(96 + f) * XS_STRIDE + n] = sv;
    }
    __syncthreads();

    mlp_core(sm, tid);
    ln_stats(sm, tid);

    for (int idx = tid; idx < TILE * 32; idx += THREADS) {
        int n = idx >> 5, f = idx & 31;
        int gn = n0 + n;
        if (gn < N) {
            float v = (Ys[n * YS_STRIDE + f] - mus[n]) * rss[n] * sm[GAM_OFF + f]
                      + sm[BET_OFF + f];
            out_node[(size_t)gn * 32 + f] = v;
            atomicAdd(&aggs[bat_s[n] * 32 + f], v);
        }
    }
    __syncthreads();
    for (int i = tid; i < 64 * 32; i += THREADS)
        atomicAdd(&g_n2g[i], aggs[i]);
}

// ======================================================================
// Global kernel: one block per graph
// ======================================================================
__global__ __launch_bounds__(128)
void global_kernel(const float* __restrict__ global_attr,
                   const float* __restrict__ W1, const float* __restrict__ b1,
                   const float* __restrict__ W2, const float* __restrict__ b2,
                   float* __restrict__ out_glob)
{
    __shared__ float gin[96];
    __shared__ float hs[128];
    const int g = blockIdx.x, tid = threadIdx.x;

    if (tid < 32) {
        gin[tid]      = g_n2g[g * 32 + tid];
        gin[32 + tid] = g_e2g[g * 32 + tid];
        gin[64 + tid] = global_attr[g * 32 + tid];
    }
    __syncthreads();

    float acc = b1[tid];
#pragma unroll 8
    for (int k = 0; k < 96; k++)
        acc = fmaf(gin[k], W1[k * 128 + tid], acc);
    hs[tid] = fmaxf(acc, 0.f);
    __syncthreads();

    if (tid < 32) {
        float a2 = b2[tid];
#pragma unroll 8
        for (int l = 0; l < 128; l++)
            a2 = fmaf(hs[l], W2[l * 32 + tid], a2);
        out_glob[g * 32 + tid] = fmaxf(a2, 0.f);
    }
}

// ======================================================================
// launch
// ======================================================================
extern "C" void kernel_launch(void* const* d_in, const int* in_sizes, int n_in,
                              void* d_out, int out_size)
{
    const float* edge_attr   = (const float*)d_in[0];
    const float* node_attr   = (const float*)d_in[1];
    const float* global_attr = (const float*)d_in[2];
    const int*   edge_index  = (const int*)d_in[3];
    const int*   batch       = (const int*)d_in[4];
    const float* eW1 = (const float*)d_in[5];
    const float* eb1 = (const float*)d_in[6];
    const float* eW2 = (const float*)d_in[7];
    const float* eb2 = (const float*)d_in[8];
    const float* eg  = (const float*)d_in[9];
    const float* eB  = (const float*)d_in[10];
    const float* nW1 = (const float*)d_in[11];
    const float* nb1 = (const float*)d_in[12];
    const float* nW2 = (const float*)d_in[13];
    const float* nb2 = (const float*)d_in[14];
    const float* ng  = (const float*)d_in[15];
    const float* nB  = (const float*)d_in[16];
    const float* gW1 = (const float*)d_in[17];
    const float* gb1 = (const float*)d_in[18];
    const float* gW2 = (const float*)d_in[19];
    const float* gb2 = (const float*)d_in[20];

    const int E = in_sizes[0] / 32;
    const int N = in_sizes[1] / 32;
    const int G = in_sizes[2] / 32;

    float* out       = (float*)d_out;
    float* out_edge  = out;
    float* out_node  = out + (size_t)E * 32;
    float* out_glob  = out + (size_t)(E + N) * 32;

    // zero scratch accumulators (graph-capturable memset nodes)
    void* p;
    cudaGetSymbolAddress(&p, g_send_agg);
    cudaMemsetAsync(p, 0, (size_t)N * 32 * sizeof(float));
    cudaGetSymbolAddress(&p, g_recv_agg);
    cudaMemsetAsync(p, 0, (size_t)N * 32 * sizeof(float));
    cudaGetSymbolAddress(&p, g_e2g);
    cudaMemsetAsync(p, 0, (size_t)G * 32 * sizeof(float));
    cudaGetSymbolAddress(&p, g_n2g);
    cudaMemsetAsync(p, 0, (size_t)G * 32 * sizeof(float));

    cudaFuncSetAttribute(edge_kernel,
                         cudaFuncAttributeMaxDynamicSharedMemorySize, SMEM_BYTES);
    cudaFuncSetAttribute(node_kernel,
                         cudaFuncAttributeMaxDynamicSharedMemorySize, SMEM_BYTES);

    const int eblocks = (E + TILE - 1) / TILE;
    edge_kernel<<<eblocks, THREADS, SMEM_BYTES>>>(
        edge_attr, node_attr, global_attr, edge_index, batch,
        eW1, eb1, eW2, eb2, eg, eB, out_edge, E);

    const int nblocks = (N + TILE - 1) / TILE;
    node_kernel<<<nblocks, THREADS, SMEM_BYTES>>>(
        node_attr, global_attr, batch,
        nW1, nb1, nW2, nb2, ng, nB, out_node, N);

    global_kernel<<<G, 128>>>(global_attr, gW1, gb1, gW2, gb2, out_glob);
}

// round 3
// speedup vs baseline: 2.6086x; 2.6086x over previous
#include <cuda_runtime.h>
#include <cstdint>

// ============================================================
// Scratch (no allocs allowed)
// ============================================================
#define N_MAX 50048
__device__ float g_send_agg[N_MAX * 32];
__device__ float g_recv_agg[N_MAX * 32];
__device__ float g_e2g[64 * 32];
__device__ float g_n2g[64 * 32];
// transposed [n][k], tf32-rounded weight images
__device__ float g_ew1[128 * 128];
__device__ float g_ew2[32 * 128];
__device__ float g_nw1[128 * 128];
__device__ float g_nw2[32 * 128];

__device__ __forceinline__ uint32_t tf32r(float x) {
    uint32_t u;
    asm("cvt.rna.tf32.f32 %0, %1;" : "=r"(u) : "f"(x));
    return u;
}
__device__ __forceinline__ void red_add_v4(float* p, float a, float b, float c, float d) {
    asm volatile("red.global.add.v4.f32 [%0], {%1, %2, %3, %4};"
                 :: "l"(p), "f"(a), "f"(b), "f"(c), "f"(d) : "memory");
}
__device__ __forceinline__ void mma_tf32(float* d, const uint32_t* a, const uint32_t* b) {
    asm volatile(
        "mma.sync.aligned.m16n8k8.row.col.f32.tf32.tf32.f32 "
        "{%0,%1,%2,%3}, {%4,%5,%6,%7}, {%8,%9}, {%0,%1,%2,%3};"
        : "+f"(d[0]), "+f"(d[1]), "+f"(d[2]), "+f"(d[3])
        : "r"(a[0]), "r"(a[1]), "r"(a[2]), "r"(a[3]), "r"(b[0]), "r"(b[1]));
}

// ============================================================
// SMEM layout (float offsets).  Row stride 132 -> conflict-free frags.
// ============================================================
#define XSTR 132
#define OFF_X    0                      // 128 x 132
#define OFF_W1   (OFF_X  + 128 * XSTR)  // 128 x 132  (W1^T: [n][k])
#define OFF_W2   (OFF_W1 + 128 * XSTR)  // 32 x 132   (W2^T: [n][k])
#define OFF_Y    (OFF_W2 + 32 * XSTR)   // 128 x 33
#define YSTR 33
#define OFF_B1   (OFF_Y + 128 * YSTR)   // 128
#define OFF_B2   (OFF_B1 + 128)         // 32
#define OFF_GAM  (OFF_B2 + 32)
#define OFF_BET  (OFF_GAM + 32)
#define OFF_IDXA (OFF_BET + 32)         // 128 ints
#define OFF_IDXB (OFF_IDXA + 128)
#define OFF_IDXC (OFF_IDXB + 128)
#define SMEM_FLOATS (OFF_IDXC + 128)
#define SMEM_BYTES  (SMEM_FLOATS * 4)

#define GRID_P 148

// ============================================================
// Weight prep: W[k][n] -> W^T [n][k], tf32-rounded (dense)
// ============================================================
__global__ void prep_kernel(const float* eW1, const float* eW2,
                            const float* nW1, const float* nW2)
{
    int tid = blockIdx.x * blockDim.x + threadIdx.x;
    int nth = gridDim.x * blockDim.x;
    for (int i = tid; i < 128 * 128; i += nth) {
        int k = i >> 7, n = i & 127;
        ((uint32_t*)g_ew1)[n * 128 + k] = tf32r(eW1[i]);
        ((uint32_t*)g_nw1)[n * 128 + k] = tf32r(nW1[i]);
    }
    for (int i = tid; i < 128 * 32; i += nth) {
        int k = i >> 5, n = i & 31;
        ((uint32_t*)g_ew2)[n * 128 + k] = tf32r(eW2[i]);
        ((uint32_t*)g_nw2)[n * 128 + k] = tf32r(nW2[i]);
    }
}

// ============================================================
// Persistent fused MLP kernel.  MODE 0 = edge model, 1 = node model
// 256 threads = 8 warps.
// GEMM1 (128x128x128): warp w -> rows 32*(w>>1), cols 64*(w&1); 2 mb x 8 nb
// GEMM2 (128x32x128):  warp w -> rows 32*(w>>1), cols 16*(w&1); 2 mb x 2 nb
// ============================================================
template <int MODE>
__global__ __launch_bounds__(256, 1)
void mlp_kernel(const float* __restrict__ src_main,
                const float* __restrict__ node_attr,
                const float* __restrict__ global_attr,
                const int*   __restrict__ edge_index,
                const int*   __restrict__ batch,
                const float* __restrict__ w1img, const float* __restrict__ w2img,
                const float* __restrict__ b1g, const float* __restrict__ b2g,
                const float* __restrict__ gamg, const float* __restrict__ betg,
                float* __restrict__ out, int count, int E)
{
    extern __shared__ float sm[];
    float* Xs  = sm + OFF_X;
    float* W1s = sm + OFF_W1;
    float* W2s = sm + OFF_W2;
    float* Ys  = sm + OFF_Y;
    float* b1s = sm + OFF_B1;
    float* b2s = sm + OFF_B2;
    float* gams = sm + OFF_GAM;
    float* bets = sm + OFF_BET;
    int* idxA = (int*)(sm + OFF_IDXA);
    int* idxB = (int*)(sm + OFF_IDXB);
    int* idxC = (int*)(sm + OFF_IDXC);

    const int tid  = threadIdx.x;
    const int wid  = tid >> 5;
    const int lane = tid & 31;
    const int lg   = lane >> 2;   // group id 0..7
    const int lt   = lane & 3;    // thread-in-group 0..3

    // ---- one-time: stage weights (restride 128 -> 132) ----
    for (int i = tid; i < 128 * 32; i += 256) {
        int n = i >> 5, kq = i & 31;
        float4 v = ((const float4*)w1img)[n * 32 + kq];
        *(float4*)&W1s[n * XSTR + kq * 4] = v;
    }
    for (int i = tid; i < 32 * 32; i += 256) {
        int n = i >> 5, kq = i & 31;
        float4 v = ((const float4*)w2img)[n * 32 + kq];
        *(float4*)&W2s[n * XSTR + kq * 4] = v;
    }
    if (tid < 128) b1s[tid] = b1g[tid];
    if (tid < 32) {
        b2s[tid]  = b2g[tid];
        gams[tid] = gamg[tid];
        bets[tid] = betg[tid];
    }
    __syncthreads();

    const int ntiles = (count + 127) >> 7;
    for (int t = blockIdx.x; t < ntiles; t += gridDim.x) {
        const int t0 = t << 7;

        // ---- indices ----
        if (tid < 128) {
            int g = t0 + tid;
            if (MODE == 0) {
                int r = 0, c = 0;
                if (g < count) { r = edge_index[g]; c = edge_index[E + g]; }
                idxA[tid] = r; idxB[tid] = c; idxC[tid] = batch[r];
            } else {
                idxA[tid] = (g < count) ? batch[g] : 0;
            }
        }
        __syncthreads();

        // ---- gather X[m][k] (tf32-rounded), 4 segments of 32 ----
        for (int i = tid; i < 1024; i += 256) {
            int e = i >> 3, q = i & 7;
            int g = t0 + e;
            float4 z = make_float4(0.f, 0.f, 0.f, 0.f);
            float4 v0 = z, v1 = z, v2 = z, v3 = z;
            if (g < count) {
                if (MODE == 0) {
                    v0 = *(const float4*)(node_attr + (size_t)idxB[e] * 32 + q * 4);
                    v1 = *(const float4*)(node_attr + (size_t)idxA[e] * 32 + q * 4);
                    v2 = *(const float4*)(src_main + (size_t)g * 32 + q * 4);
                    v3 = *(const float4*)(global_attr + (size_t)idxC[e] * 32 + q * 4);
                } else {
                    v0 = *(const float4*)(src_main + (size_t)g * 32 + q * 4);
                    v1 = *(const float4*)(global_attr + (size_t)idxA[e] * 32 + q * 4);
                    v2 = *(const float4*)(g_recv_agg + (size_t)g * 32 + q * 4);
                    v3 = *(const float4*)(g_send_agg + (size_t)g * 32 + q * 4);
                }
            }
            uint4 w;
            float* row = Xs + e * XSTR;
            w.x = tf32r(v0.x); w.y = tf32r(v0.y); w.z = tf32r(v0.z); w.w = tf32r(v0.w);
            *(uint4*)(row + q * 4) = w;
            w.x = tf32r(v1.x); w.y = tf32r(v1.y); w.z = tf32r(v1.z); w.w = tf32r(v1.w);
            *(uint4*)(row + 32 + q * 4) = w;
            w.x = tf32r(v2.x); w.y = tf32r(v2.y); w.z = tf32r(v2.z); w.w = tf32r(v2.w);
            *(uint4*)(row + 64 + q * 4) = w;
            w.x = tf32r(v3.x); w.y = tf32r(v3.y); w.z = tf32r(v3.z); w.w = tf32r(v3.w);
            *(uint4*)(row + 96 + q * 4) = w;
        }
        __syncthreads();

        // ================= GEMM1: H = relu(X @ W1 + b1) =================
        {
            const int rbase = 32 * (wid >> 1);
            const int nbase = 64 * (wid & 1);
            float acc[2][8][4];
#pragma unroll
            for (int mb = 0; mb < 2; mb++)
#pragma unroll
                for (int nb = 0; nb < 8; nb++)
#pragma unroll
                    for (int f = 0; f < 4; f++) acc[mb][nb][f] = 0.f;

#pragma unroll
            for (int s = 0; s < 16; s++) {
                const int k0 = 8 * s;
                uint32_t a[2][4];
#pragma unroll
                for (int mb = 0; mb < 2; mb++) {
                    const float* p = Xs + (rbase + 16 * mb + lg) * XSTR + k0 + lt;
                    a[mb][0] = __float_as_uint(p[0]);
                    a[mb][1] = __float_as_uint(p[8 * XSTR]);
                    a[mb][2] = __float_as_uint(p[4]);
                    a[mb][3] = __float_as_uint(p[8 * XSTR + 4]);
                }
                uint32_t b[8][2];
#pragma unroll
                for (int nb = 0; nb < 8; nb++) {
                    const float* p = W1s + (nbase + 8 * nb + lg) * XSTR + k0 + lt;
                    b[nb][0] = __float_as_uint(p[0]);
                    b[nb][1] = __float_as_uint(p[4]);
                }
#pragma unroll
                for (int mb = 0; mb < 2; mb++)
#pragma unroll
                    for (int nb = 0; nb < 8; nb++)
                        mma_tf32(acc[mb][nb], a[mb], b[nb]);
            }
            __syncthreads();   // all X/W1 reads done before H overwrites Xs

            // epilogue1: relu(+b1), tf32-round, store H into Xs[m][l]
#pragma unroll
            for (int nb = 0; nb < 8; nb++) {
                const int c0 = nbase + 8 * nb + 2 * lt;
                const float bb0 = b1s[c0], bb1 = b1s[c0 + 1];
#pragma unroll
                for (int mb = 0; mb < 2; mb++) {
                    const int r0 = rbase + 16 * mb + lg;
                    uint32_t h0 = tf32r(fmaxf(acc[mb][nb][0] + bb0, 0.f));
                    uint32_t h1 = tf32r(fmaxf(acc[mb][nb][1] + bb1, 0.f));
                    uint32_t h2 = tf32r(fmaxf(acc[mb][nb][2] + bb0, 0.f));
                    uint32_t h3 = tf32r(fmaxf(acc[mb][nb][3] + bb1, 0.f));
                    *(uint2*)&Xs[r0 * XSTR + c0]       = make_uint2(h0, h1);
                    *(uint2*)&Xs[(r0 + 8) * XSTR + c0] = make_uint2(h2, h3);
                }
            }
        }
        __syncthreads();

        // ================= GEMM2: Y = relu(H @ W2 + b2) =================
        {
            const int rbase = 32 * (wid >> 1);
            const int nbase = 16 * (wid & 1);
            float acc[2][2][4];
#pragma unroll
            for (int mb = 0; mb < 2; mb++)
#pragma unroll
                for (int nb = 0; nb < 2; nb++)
#pragma unroll
                    for (int f = 0; f < 4; f++) acc[mb][nb][f] = 0.f;

#pragma unroll
            for (int s = 0; s < 16; s++) {
                const int k0 = 8 * s;
                uint32_t a[2][4];
#pragma unroll
                for (int mb = 0; mb < 2; mb++) {
                    const float* p = Xs + (rbase + 16 * mb + lg) * XSTR + k0 + lt;
                    a[mb][0] = __float_as_uint(p[0]);
                    a[mb][1] = __float_as_uint(p[8 * XSTR]);
                    a[mb][2] = __float_as_uint(p[4]);
                    a[mb][3] = __float_as_uint(p[8 * XSTR + 4]);
                }
                uint32_t b[2][2];
#pragma unroll
                for (int nb = 0; nb < 2; nb++) {
                    const float* p = W2s + (nbase + 8 * nb + lg) * XSTR + k0 + lt;
                    b[nb][0] = __float_as_uint(p[0]);
                    b[nb][1] = __float_as_uint(p[4]);
                }
#pragma unroll
                for (int mb = 0; mb < 2; mb++)
#pragma unroll
                    for (int nb = 0; nb < 2; nb++)
                        mma_tf32(acc[mb][nb], a[mb], b[nb]);
            }

            // store relu(+b2) to Ys (fp32, no rounding)
#pragma unroll
            for (int nb = 0; nb < 2; nb++) {
                const int c0 = nbase + 8 * nb + 2 * lt;
                const float bb0 = b2s[c0], bb1 = b2s[c0 + 1];
#pragma unroll
                for (int mb = 0; mb < 2; mb++) {
                    const int r0 = rbase + 16 * mb + lg;
                    Ys[r0 * YSTR + c0]           = fmaxf(acc[mb][nb][0] + bb0, 0.f);
                    Ys[r0 * YSTR + c0 + 1]       = fmaxf(acc[mb][nb][1] + bb1, 0.f);
                    Ys[(r0 + 8) * YSTR + c0]     = fmaxf(acc[mb][nb][2] + bb0, 0.f);
                    Ys[(r0 + 8) * YSTR + c0 + 1] = fmaxf(acc[mb][nb][3] + bb1, 0.f);
                }
            }
        }
        __syncthreads();

        // ================= LN + store + scatter-red =================
        if (tid < 128) {
            int g = t0 + tid;
            if (g < count) {
                float y[32];
                float s = 0.f, s2 = 0.f;
#pragma unroll
                for (int c = 0; c < 32; c++) {
                    float v = Ys[tid * YSTR + c];
                    y[c] = v;
                    s += v;
                    s2 = fmaf(v, v, s2);
                }
                float mu = s * (1.f / 32.f);
                float rs = rsqrtf(fmaxf(s2 * (1.f / 32.f) - mu * mu, 0.f) + 1e-5f);
#pragma unroll
                for (int c = 0; c < 32; c++)
                    y[c] = (y[c] - mu) * rs * gams[c] + bets[c];

                float4* op = (float4*)(out + (size_t)g * 32);
#pragma unroll
                for (int q = 0; q < 8; q++)
                    op[q] = make_float4(y[4 * q], y[4 * q + 1], y[4 * q + 2], y[4 * q + 3]);

                if (MODE == 0) {
                    float* ps = g_send_agg + (size_t)idxA[tid] * 32;
                    float* pr = g_recv_agg + (size_t)idxB[tid] * 32;
                    float* pg = g_e2g + (size_t)idxC[tid] * 32;
#pragma unroll
                    for (int q = 0; q < 8; q++) {
                        red_add_v4(ps + 4 * q, y[4 * q], y[4 * q + 1], y[4 * q + 2], y[4 * q + 3]);
                        red_add_v4(pr + 4 * q, y[4 * q], y[4 * q + 1], y[4 * q + 2], y[4 * q + 3]);
                        red_add_v4(pg + 4 * q, y[4 * q], y[4 * q + 1], y[4 * q + 2], y[4 * q + 3]);
                    }
                } else {
                    float* pg = g_n2g + (size_t)idxA[tid] * 32;
#pragma unroll
                    for (int q = 0; q < 8; q++)
                        red_add_v4(pg + 4 * q, y[4 * q], y[4 * q + 1], y[4 * q + 2], y[4 * q + 3]);
                }
            }
        }
        __syncthreads();   // protect Xs/Ys/idx for next tile
    }
}

// ============================================================
// Global model (tiny)
// ============================================================
__global__ __launch_bounds__(128)
void global_kernel(const float* __restrict__ global_attr,
                   const float* __restrict__ W1, const float* __restrict__ b1,
                   const float* __restrict__ W2, const float* __restrict__ b2,
                   float* __restrict__ out_glob)
{
    __shared__ float gin[96];
    __shared__ float hs[128];
    const int g = blockIdx.x, tid = threadIdx.x;
    if (tid < 32) {
        gin[tid]      = g_n2g[g * 32 + tid];
        gin[32 + tid] = g_e2g[g * 32 + tid];
        gin[64 + tid] = global_attr[g * 32 + tid];
    }
    __syncthreads();
    float acc = b1[tid];
#pragma unroll 8
    for (int k = 0; k < 96; k++)
        acc = fmaf(gin[k], W1[k * 128 + tid], acc);
    hs[tid] = fmaxf(acc, 0.f);
    __syncthreads();
    if (tid < 32) {
        float a2 = b2[tid];
#pragma unroll 8
        for (int l = 0; l < 128; l++)
            a2 = fmaf(hs[l], W2[l * 32 + tid], a2);
        out_glob[g * 32 + tid] = fmaxf(a2, 0.f);
    }
}

// ============================================================
// launch
// ============================================================
extern "C" void kernel_launch(void* const* d_in, const int* in_sizes, int n_in,
                              void* d_out, int out_size)
{
    const float* edge_attr   = (const float*)d_in[0];
    const float* node_attr   = (const float*)d_in[1];
    const float* global_attr = (const float*)d_in[2];
    const int*   edge_index  = (const int*)d_in[3];
    const int*   batch       = (const int*)d_in[4];
    const float* eW1 = (const float*)d_in[5];
    const float* eb1 = (const float*)d_in[6];
    const float* eW2 = (const float*)d_in[7];
    const float* eb2 = (const float*)d_in[8];
    const float* eg  = (const float*)d_in[9];
    const float* eB  = (const float*)d_in[10];
    const float* nW1 = (const float*)d_in[11];
    const float* nb1 = (const float*)d_in[12];
    const float* nW2 = (const float*)d_in[13];
    const float* nb2 = (const float*)d_in[14];
    const float* ng  = (const float*)d_in[15];
    const float* nB  = (const float*)d_in[16];
    const float* gW1 = (const float*)d_in[17];
    const float* gb1 = (const float*)d_in[18];
    const float* gW2 = (const float*)d_in[19];
    const float* gb2 = (const float*)d_in[20];

    const int E = in_sizes[0] / 32;
    const int N = in_sizes[1] / 32;
    const int G = in_sizes[2] / 32;

    float* out      = (float*)d_out;
    float* out_edge = out;
    float* out_node = out + (size_t)E * 32;
    float* out_glob = out + (size_t)(E + N) * 32;

    void* p;
    cudaGetSymbolAddress(&p, g_send_agg);
    cudaMemsetAsync(p, 0, (size_t)N * 32 * sizeof(float));
    cudaGetSymbolAddress(&p, g_recv_agg);
    cudaMemsetAsync(p, 0, (size_t)N * 32 * sizeof(float));
    cudaGetSymbolAddress(&p, g_e2g);
    cudaMemsetAsync(p, 0, (size_t)G * 32 * sizeof(float));
    cudaGetSymbolAddress(&p, g_n2g);
    cudaMemsetAsync(p, 0, (size_t)G * 32 * sizeof(float));

    prep_kernel<<<8, 256>>>(eW1, eW2, nW1, nW2);

    cudaFuncSetAttribute(mlp_kernel<0>, cudaFuncAttributeMaxDynamicSharedMemorySize, SMEM_BYTES);
    cudaFuncSetAttribute(mlp_kernel<1>, cudaFuncAttributeMaxDynamicSharedMemorySize, SMEM_BYTES);

    float *ew1p, *ew2p, *nw1p, *nw2p;
    cudaGetSymbolAddress((void**)&ew1p, g_ew1);
    cudaGetSymbolAddress((void**)&ew2p, g_ew2);
    cudaGetSymbolAddress((void**)&nw1p, g_nw1);
    cudaGetSymbolAddress((void**)&nw2p, g_nw2);

    mlp_kernel<0><<<GRID_P, 256, SMEM_BYTES>>>(
        edge_attr, node_attr, global_attr, edge_index, batch,
        ew1p, ew2p, eb1, eb2, eg, eB, out_edge, E, E);

    mlp_kernel<1><<<GRID_P, 256, SMEM_BYTES>>>(
        node_attr, node_attr, global_attr, edge_index, batch,
        nw1p, nw2p, nb1, nb2, ng, nB, out_node, N, E);

    global_kernel<<<G, 128>>>(global_attr, gW1, gb1, gW2, gb2, out_glob);
}

// round 6
// speedup vs baseline: 2.7775x; 1.0647x over previous
#include <cuda_runtime.h>
#include <cstdint>

// ============================================================
// Scratch (no allocs allowed)
// ============================================================
#define N_MAX 50048
__device__ float g_send_agg[N_MAX * 32];
__device__ float g_recv_agg[N_MAX * 32];
__device__ float g_e2g[64 * 32];
__device__ float g_n2g[64 * 32];
// transposed [n][k], tf32-rounded weight images
__device__ float g_ew1[128 * 128];
__device__ float g_ew2[32 * 128];
__device__ float g_nw1[128 * 128];
__device__ float g_nw2[32 * 128];

__device__ __forceinline__ uint32_t tf32r(float x) {
    uint32_t u;
    asm("cvt.rna.tf32.f32 %0, %1;" : "=r"(u) : "f"(x));
    return u;
}
__device__ __forceinline__ void red_add_v4(float* p, float a, float b, float c, float d) {
    asm volatile("red.global.add.v4.f32 [%0], {%1, %2, %3, %4};"
                 :: "l"(p), "f"(a), "f"(b), "f"(c), "f"(d) : "memory");
}
__device__ __forceinline__ void mma_tf32(float* d, const uint32_t* a, const uint32_t* b) {
    asm volatile(
        "mma.sync.aligned.m16n8k8.row.col.f32.tf32.tf32.f32 "
        "{%0,%1,%2,%3}, {%4,%5,%6,%7}, {%8,%9}, {%0,%1,%2,%3};"
        : "+f"(d[0]), "+f"(d[1]), "+f"(d[2]), "+f"(d[3])
        : "r"(a[0]), "r"(a[1]), "r"(a[2]), "r"(a[3]), "r"(b[0]), "r"(b[1]));
}
__device__ __forceinline__ uint32_t smem_u32(const void* p) {
    uint32_t a;
    asm("{ .reg .u64 t; cvta.to.shared.u64 t, %1; cvt.u32.u64 %0, t; }" : "=r"(a) : "l"(p));
    return a;
}
#define LDSM_X4(r0, r1, r2, r3, addr) \
    asm volatile("ldmatrix.sync.aligned.m8n8.x4.shared.b16 {%0,%1,%2,%3}, [%4];" \
                 : "=r"(r0), "=r"(r1), "=r"(r2), "=r"(r3) : "r"(addr))

// ============================================================
// SMEM layout (float offsets).  Row stride 132 -> conflict-free LDSM phases
// (132 mod 32 = 4: 8 rows per phase hit banks {4r..4r+3}, all 32 exactly once)
// ============================================================
#define XSTR 132
#define OFF_X    0                      // 128 x 132
#define OFF_W1   (OFF_X  + 128 * XSTR)  // 128 x 132  (W1^T: [n][k])
#define OFF_W2   (OFF_W1 + 128 * XSTR)  // 32 x 132   (W2^T: [n][k])
#define OFF_Y    (OFF_W2 + 32 * XSTR)   // 128 x 33
#define YSTR 33
#define OFF_B1   (OFF_Y + 128 * YSTR)
#define OFF_B2   (OFF_B1 + 128)
#define OFF_GAM  (OFF_B2 + 32)
#define OFF_BET  (OFF_GAM + 32)
#define OFF_IDXA (OFF_BET + 32)
#define OFF_IDXB (OFF_IDXA + 128)
#define OFF_IDXC (OFF_IDXB + 128)
#define SMEM_FLOATS (OFF_IDXC + 128)
#define SMEM_BYTES  (SMEM_FLOATS * 4)

#define GRID_P 148

// ============================================================
// Weight prep: W[k][n] -> W^T [n][k], tf32-rounded
// ============================================================
__global__ void prep_kernel(const float* eW1, const float* eW2,
                            const float* nW1, const float* nW2)
{
    int tid = blockIdx.x * blockDim.x + threadIdx.x;
    int nth = gridDim.x * blockDim.x;
    for (int i = tid; i < 128 * 128; i += nth) {
        int k = i >> 7, n = i & 127;
        ((uint32_t*)g_ew1)[n * 128 + k] = tf32r(eW1[i]);
        ((uint32_t*)g_nw1)[n * 128 + k] = tf32r(nW1[i]);
    }
    for (int i = tid; i < 128 * 32; i += nth) {
        int k = i >> 5, n = i & 31;
        ((uint32_t*)g_ew2)[n * 128 + k] = tf32r(eW2[i]);
        ((uint32_t*)g_nw2)[n * 128 + k] = tf32r(nW2[i]);
    }
}

// ============================================================
// Persistent fused MLP kernel.  MODE 0 = edge model, 1 = node model
// 256 threads = 8 warps.
// GEMM1: warp w -> rows 32*(w>>1), cols 64*(w&1); 2 mb x 8 nb
// GEMM2: warp w -> rows 32*(w>>1), cols 16*(w&1); 2 mb x 2 nb
// All fragments loaded via ldmatrix.x4 (tf32 == b16-pair trick).
// ============================================================
template <int MODE>
__global__ __launch_bounds__(256, 1)
void mlp_kernel(const float* __restrict__ src_main,
                const float* __restrict__ node_attr,
                const float* __restrict__ global_attr,
                const int*   __restrict__ edge_index,
                const int*   __restrict__ batch,
                const float* __restrict__ w1img, const float* __restrict__ w2img,
                const float* __restrict__ b1g, const float* __restrict__ b2g,
                const float* __restrict__ gamg, const float* __restrict__ betg,
                float* __restrict__ out, int count, int E)
{
    extern __shared__ float sm[];
    float* Xs  = sm + OFF_X;
    float* W1s = sm + OFF_W1;
    float* W2s = sm + OFF_W2;
    float* Ys  = sm + OFF_Y;
    float* b1s = sm + OFF_B1;
    float* b2s = sm + OFF_B2;
    float* gams = sm + OFF_GAM;
    float* bets = sm + OFF_BET;
    int* idxA = (int*)(sm + OFF_IDXA);
    int* idxB = (int*)(sm + OFF_IDXB);
    int* idxC = (int*)(sm + OFF_IDXC);

    const int tid  = threadIdx.x;
    const int wid  = tid >> 5;
    const int lane = tid & 31;
    const int lt   = lane & 3;    // for epilogues

    // ldmatrix per-lane source row/col offsets
    const int m4    = lane >> 3;                   // which 8x8 matrix
    const int aRow  = ((m4 & 1) << 3) + (lane & 7); // A: m0/m2 rows 0-7, m1/m3 rows 8-15
    const int aKoff = (m4 >> 1) << 2;               // A: m0/m1 k 0-3, m2/m3 k 4-7
    const int bNrow = ((m4 >> 1) << 3) + (lane & 7);// B: m0/m1 n 0-7, m2/m3 n 8-15
    const int bKoff = (m4 & 1) << 2;                // B: m0/m2 k 0-3, m1/m3 k 4-7

    const uint32_t xs_u  = smem_u32(Xs);
    const uint32_t w1_u  = smem_u32(W1s);
    const uint32_t w2_u  = smem_u32(W2s);

    // ---- one-time: stage weights (restride 128 -> 132) ----
    for (int i = tid; i < 128 * 32; i += 256) {
        int n = i >> 5, kq = i & 31;
        float4 v = ((const float4*)w1img)[n * 32 + kq];
        *(float4*)&W1s[n * XSTR + kq * 4] = v;
    }
    for (int i = tid; i < 32 * 32; i += 256) {
        int n = i >> 5, kq = i & 31;
        float4 v = ((const float4*)w2img)[n * 32 + kq];
        *(float4*)&W2s[n * XSTR + kq * 4] = v;
    }
    if (tid < 128) b1s[tid] = b1g[tid];
    if (tid < 32) {
        b2s[tid]  = b2g[tid];
        gams[tid] = gamg[tid];
        bets[tid] = betg[tid];
    }
    __syncthreads();

    const int ntiles = (count + 127) >> 7;
    for (int t = blockIdx.x; t < ntiles; t += gridDim.x) {
        const int t0 = t << 7;

        // ---- indices ----
        if (tid < 128) {
            int g = t0 + tid;
            if (MODE == 0) {
                int r = 0, c = 0;
                if (g < count) { r = edge_index[g]; c = edge_index[E + g]; }
                idxA[tid] = r; idxB[tid] = c; idxC[tid] = batch[r];
            } else {
                idxA[tid] = (g < count) ? batch[g] : 0;
            }
        }
        __syncthreads();

        // ---- gather X[m][k] (tf32-rounded) ----
        for (int i = tid; i < 1024; i += 256) {
            int e = i >> 3, q = i & 7;
            int g = t0 + e;
            float4 z = make_float4(0.f, 0.f, 0.f, 0.f);
            float4 v0 = z, v1 = z, v2 = z, v3 = z;
            if (g < count) {
                if (MODE == 0) {
                    v0 = *(const float4*)(node_attr + (size_t)idxB[e] * 32 + q * 4);
                    v1 = *(const float4*)(node_attr + (size_t)idxA[e] * 32 + q * 4);
                    v2 = *(const float4*)(src_main + (size_t)g * 32 + q * 4);
                    v3 = *(const float4*)(global_attr + (size_t)idxC[e] * 32 + q * 4);
                } else {
                    v0 = *(const float4*)(src_main + (size_t)g * 32 + q * 4);
                    v1 = *(const float4*)(global_attr + (size_t)idxA[e] * 32 + q * 4);
                    v2 = *(const float4*)(g_recv_agg + (size_t)g * 32 + q * 4);
                    v3 = *(const float4*)(g_send_agg + (size_t)g * 32 + q * 4);
                }
            }
            uint4 w;
            float* row = Xs + e * XSTR;
            w.x = tf32r(v0.x); w.y = tf32r(v0.y); w.z = tf32r(v0.z); w.w = tf32r(v0.w);
            *(uint4*)(row + q * 4) = w;
            w.x = tf32r(v1.x); w.y = tf32r(v1.y); w.z = tf32r(v1.z); w.w = tf32r(v1.w);
            *(uint4*)(row + 32 + q * 4) = w;
            w.x = tf32r(v2.x); w.y = tf32r(v2.y); w.z = tf32r(v2.z); w.w = tf32r(v2.w);
            *(uint4*)(row + 64 + q * 4) = w;
            w.x = tf32r(v3.x); w.y = tf32r(v3.y); w.z = tf32r(v3.z); w.w = tf32r(v3.w);
            *(uint4*)(row + 96 + q * 4) = w;
        }
        __syncthreads();

        // ================= GEMM1: H = relu(X @ W1 + b1) =================
        {
            const int rbase = 32 * (wid >> 1);
            const int nbase = 64 * (wid & 1);
            // per-lane ldmatrix base addresses (bytes)
            const uint32_t aBase0 = xs_u + (uint32_t)(((rbase + aRow) * XSTR + aKoff) * 4);
            const uint32_t aBase1 = aBase0 + 16u * XSTR * 4u;
            const uint32_t bBaseW1 = w1_u + (uint32_t)(((nbase + bNrow) * XSTR + bKoff) * 4);

            float acc[2][8][4];
#pragma unroll
            for (int mb = 0; mb < 2; mb++)
#pragma unroll
                for (int nb = 0; nb < 8; nb++)
#pragma unroll
                    for (int f = 0; f < 4; f++) acc[mb][nb][f] = 0.f;

#pragma unroll
            for (int s = 0; s < 16; s++) {
                const uint32_t kb = 32u * s;  // k0*4 bytes
                uint32_t a[2][4];
                LDSM_X4(a[0][0], a[0][1], a[0][2], a[0][3], aBase0 + kb);
                LDSM_X4(a[1][0], a[1][1], a[1][2], a[1][3], aBase1 + kb);
                uint32_t b[8][2];
#pragma unroll
                for (int p = 0; p < 4; p++) {
                    LDSM_X4(b[2 * p][0], b[2 * p][1], b[2 * p + 1][0], b[2 * p + 1][1],
                            bBaseW1 + (uint32_t)(16 * p * XSTR * 4) + kb);
                }
#pragma unroll
                for (int mb = 0; mb < 2; mb++)
#pragma unroll
                    for (int nb = 0; nb < 8; nb++)
                        mma_tf32(acc[mb][nb], a[mb], b[nb]);
            }
            __syncthreads();   // all X/W1 reads done before H overwrites Xs

            // epilogue1: relu(+b1), tf32-round, store H into Xs[m][l]
            const int lg = lane >> 2;
#pragma unroll
            for (int nb = 0; nb < 8; nb++) {
                const int c0 = nbase + 8 * nb + 2 * lt;
                const float bb0 = b1s[c0], bb1 = b1s[c0 + 1];
#pragma unroll
                for (int mb = 0; mb < 2; mb++) {
                    const int r0 = rbase + 16 * mb + lg;
                    uint32_t h0 = tf32r(fmaxf(acc[mb][nb][0] + bb0, 0.f));
                    uint32_t h1 = tf32r(fmaxf(acc[mb][nb][1] + bb1, 0.f));
                    uint32_t h2 = tf32r(fmaxf(acc[mb][nb][2] + bb0, 0.f));
                    uint32_t h3 = tf32r(fmaxf(acc[mb][nb][3] + bb1, 0.f));
                    *(uint2*)&Xs[r0 * XSTR + c0]       = make_uint2(h0, h1);
                    *(uint2*)&Xs[(r0 + 8) * XSTR + c0] = make_uint2(h2, h3);
                }
            }
        }
        __syncthreads();

        // ================= GEMM2: Y = relu(H @ W2 + b2) =================
        {
            const int rbase = 32 * (wid >> 1);
            const int nbase = 16 * (wid & 1);
            const uint32_t aBase0 = xs_u + (uint32_t)(((rbase + aRow) * XSTR + aKoff) * 4);
            const uint32_t aBase1 = aBase0 + 16u * XSTR * 4u;
            const uint32_t bBaseW2 = w2_u + (uint32_t)(((nbase + bNrow) * XSTR + bKoff) * 4);

            float acc[2][2][4];
#pragma unroll
            for (int mb = 0; mb < 2; mb++)
#pragma unroll
                for (int nb = 0; nb < 2; nb++)
#pragma unroll
                    for (int f = 0; f < 4; f++) acc[mb][nb][f] = 0.f;

#pragma unroll
            for (int s = 0; s < 16; s++) {
                const uint32_t kb = 32u * s;
                uint32_t a[2][4];
                LDSM_X4(a[0][0], a[0][1], a[0][2], a[0][3], aBase0 + kb);
                LDSM_X4(a[1][0], a[1][1], a[1][2], a[1][3], aBase1 + kb);
                uint32_t b[2][2];
                LDSM_X4(b[0][0], b[0][1], b[1][0], b[1][1], bBaseW2 + kb);
#pragma unroll
                for (int mb = 0; mb < 2; mb++)
#pragma unroll
                    for (int nb = 0; nb < 2; nb++)
                        mma_tf32(acc[mb][nb], a[mb], b[nb]);
            }

            // store relu(+b2) to Ys (fp32)
            const int lg = lane >> 2;
#pragma unroll
            for (int nb = 0; nb < 2; nb++) {
                const int c0 = nbase + 8 * nb + 2 * lt;
                const float bb0 = b2s[c0], bb1 = b2s[c0 + 1];
#pragma unroll
                for (int mb = 0; mb < 2; mb++) {
                    const int r0 = rbase + 16 * mb + lg;
                    Ys[r0 * YSTR + c0]           = fmaxf(acc[mb][nb][0] + bb0, 0.f);
                    Ys[r0 * YSTR + c0 + 1]       = fmaxf(acc[mb][nb][1] + bb1, 0.f);
                    Ys[(r0 + 8) * YSTR + c0]     = fmaxf(acc[mb][nb][2] + bb0, 0.f);
                    Ys[(r0 + 8) * YSTR + c0 + 1] = fmaxf(acc[mb][nb][3] + bb1, 0.f);
                }
            }
        }
        __syncthreads();

        // ================= LN + store + scatter-red =================
        if (tid < 128) {
            int g = t0 + tid;
            if (g < count) {
                float y[32];
                float s = 0.f, s2 = 0.f;
#pragma unroll
                for (int c = 0; c < 32; c++) {
                    float v = Ys[tid * YSTR + c];
                    y[c] = v;
                    s += v;
                    s2 = fmaf(v, v, s2);
                }
                float mu = s * (1.f / 32.f);
                float rs = rsqrtf(fmaxf(s2 * (1.f / 32.f) - mu * mu, 0.f) + 1e-5f);
#pragma unroll
                for (int c = 0; c < 32; c++)
                    y[c] = (y[c] - mu) * rs * gams[c] + bets[c];

                float4* op = (float4*)(out + (size_t)g * 32);
#pragma unroll
                for (int q = 0; q < 8; q++)
                    op[q] = make_float4(y[4 * q], y[4 * q + 1], y[4 * q + 2], y[4 * q + 3]);

                if (MODE == 0) {
                    float* ps = g_send_agg + (size_t)idxA[tid] * 32;
                    float* pr = g_recv_agg + (size_t)idxB[tid] * 32;
                    float* pg = g_e2g + (size_t)idxC[tid] * 32;
#pragma unroll
                    for (int q = 0; q < 8; q++) {
                        red_add_v4(ps + 4 * q, y[4 * q], y[4 * q + 1], y[4 * q + 2], y[4 * q + 3]);
                        red_add_v4(pr + 4 * q, y[4 * q], y[4 * q + 1], y[4 * q + 2], y[4 * q + 3]);
                        red_add_v4(pg + 4 * q, y[4 * q], y[4 * q + 1], y[4 * q + 2], y[4 * q + 3]);
                    }
                } else {
                    float* pg = g_n2g + (size_t)idxA[tid] * 32;
#pragma unroll
                    for (int q = 0; q < 8; q++)
                        red_add_v4(pg + 4 * q, y[4 * q], y[4 * q + 1], y[4 * q + 2], y[4 * q + 3]);
                }
            }
        }
        __syncthreads();   // protect Xs/Ys/idx for next tile
    }
}

// ============================================================
// Global model (tiny)
// ============================================================
__global__ __launch_bounds__(128)
void global_kernel(const float* __restrict__ global_attr,
                   const float* __restrict__ W1, const float* __restrict__ b1,
                   const float* __restrict__ W2, const float* __restrict__ b2,
                   float* __restrict__ out_glob)
{
    __shared__ float gin[96];
    __shared__ float hs[128];
    const int g = blockIdx.x, tid = threadIdx.x;
    if (tid < 32) {
        gin[tid]      = g_n2g[g * 32 + tid];
        gin[32 + tid] = g_e2g[g * 32 + tid];
        gin[64 + tid] = global_attr[g * 32 + tid];
    }
    __syncthreads();
    float acc = b1[tid];
#pragma unroll 8
    for (int k = 0; k < 96; k++)
        acc = fmaf(gin[k], W1[k * 128 + tid], acc);
    hs[tid] = fmaxf(acc, 0.f);
    __syncthreads();
    if (tid < 32) {
        float a2 = b2[tid];
#pragma unroll 8
        for (int l = 0; l < 128; l++)
            a2 = fmaf(hs[l], W2[l * 32 + tid], a2);
        out_glob[g * 32 + tid] = fmaxf(a2, 0.f);
    }
}

// ============================================================
// launch
// ============================================================
extern "C" void kernel_launch(void* const* d_in, const int* in_sizes, int n_in,
                              void* d_out, int out_size)
{
    const float* edge_attr   = (const float*)d_in[0];
    const float* node_attr   = (const float*)d_in[1];
    const float* global_attr = (const float*)d_in[2];
    const int*   edge_index  = (const int*)d_in[3];
    const int*   batch       = (const int*)d_in[4];
    const float* eW1 = (const float*)d_in[5];
    const float* eb1 = (const float*)d_in[6];
    const float* eW2 = (const float*)d_in[7];
    const float* eb2 = (const float*)d_in[8];
    const float* eg  = (const float*)d_in[9];
    const float* eB  = (const float*)d_in[10];
    const float* nW1 = (const float*)d_in[11];
    const float* nb1 = (const float*)d_in[12];
    const float* nW2 = (const float*)d_in[13];
    const float* nb2 = (const float*)d_in[14];
    const float* ng  = (const float*)d_in[15];
    const float* nB  = (const float*)d_in[16];
    const float* gW1 = (const float*)d_in[17];
    const float* gb1 = (const float*)d_in[18];
    const float* gW2 = (const float*)d_in[19];
    const float* gb2 = (const float*)d_in[20];

    const int E = in_sizes[0] / 32;
    const int N = in_sizes[1] / 32;
    const int G = in_sizes[2] / 32;

    float* out      = (float*)d_out;
    float* out_edge = out;
    float* out_node = out + (size_t)E * 32;
    float* out_glob = out + (size_t)(E + N) * 32;

    void* p;
    cudaGetSymbolAddress(&p, g_send_agg);
    cudaMemsetAsync(p, 0, (size_t)N * 32 * sizeof(float));
    cudaGetSymbolAddress(&p, g_recv_agg);
    cudaMemsetAsync(p, 0, (size_t)N * 32 * sizeof(float));
    cudaGetSymbolAddress(&p, g_e2g);
    cudaMemsetAsync(p, 0, (size_t)G * 32 * sizeof(float));
    cudaGetSymbolAddress(&p, g_n2g);
    cudaMemsetAsync(p, 0, (size_t)G * 32 * sizeof(float));

    prep_kernel<<<8, 256>>>(eW1, eW2, nW1, nW2);

    cudaFuncSetAttribute(mlp_kernel<0>, cudaFuncAttributeMaxDynamicSharedMemorySize, SMEM_BYTES);
    cudaFuncSetAttribute(mlp_kernel<1>, cudaFuncAttributeMaxDynamicSharedMemorySize, SMEM_BYTES);

    float *ew1p, *ew2p, *nw1p, *nw2p;
    cudaGetSymbolAddress((void**)&ew1p, g_ew1);
    cudaGetSymbolAddress((void**)&ew2p, g_ew2);
    cudaGetSymbolAddress((void**)&nw1p, g_nw1);
    cudaGetSymbolAddress((void**)&nw2p, g_nw2);

    mlp_kernel<0><<<GRID_P, 256, SMEM_BYTES>>>(
        edge_attr, node_attr, global_attr, edge_index, batch,
        ew1p, ew2p, eb1, eb2, eg, eB, out_edge, E, E);

    mlp_kernel<1><<<GRID_P, 256, SMEM_BYTES>>>(
        node_attr, node_attr, global_attr, edge_index, batch,
        nw1p, nw2p, nb1, nb2, ng, nB, out_node, N, E);

    global_kernel<<<G, 128>>>(global_attr, gW1, gb1, gW2, gb2, out_glob);
}